// round 3
// baseline (speedup 1.0000x reference)
#include <cuda_runtime.h>
#include <cuda_bf16.h>

// Problem constants (fixed by setup_inputs)
#define BB 32
#define GG 256
#define PP 2048
#define NC 80

// Per-block partial sums (deterministic two-stage reduction, no float atomics)
#define NBLK ((PP / 256) * BB)   // 8 * 32 = 256
__device__ float g_partial[NBLK];

// ---------------------------------------------------------------------------
// Kernel 1 (fused): build class-compacted target lists, histogram pre_labels,
// compute GIoU against same-class targets only (tracking max target index),
// reduce per block.
// Grid: (PP/256, BB) x 256 threads. One thread = one prediction.
// ---------------------------------------------------------------------------
__global__ void __launch_bounds__(256)
giou_kernel(const float4* __restrict__ imgs_box,
            const int*    __restrict__ img_labels,
            const float4* __restrict__ pre_box,
            const int*    __restrict__ pre_label) {
    // Class-compacted target SoA (order within a class is arbitrary).
    __shared__ float p0[GG], p1[GG], p2[GG], p3[GG], pa_s[GG];
    __shared__ int   pg[GG];             // original target index g
    __shared__ int   cnt_t[NC];          // targets per class
    __shared__ int   start[NC];          // exclusive prefix sum of cnt_t
    __shared__ int   cursor[NC];         // scatter cursors
    __shared__ int   cnt_p[NC];          // pre_label histogram (weights)
    __shared__ float warp_sums[8];

    const int b   = blockIdx.y;
    const int tid = threadIdx.x;

    if (tid < NC) { cnt_t[tid] = 0; cursor[tid] = 0; cnt_p[tid] = 0; }
    __syncthreads();

    // Target label histogram (one target per thread).
    const int tlab = img_labels[b * GG + tid];
    atomicAdd(&cnt_t[tlab], 1);

    // Pre-label histogram for the weight lookup.
    {
        const int* lab = pre_label + b * PP;
        #pragma unroll
        for (int i = 0; i < PP / 256; ++i)
            atomicAdd(&cnt_p[lab[tid + i * 256]], 1);
    }
    __syncthreads();

    // Exclusive prefix sum over 80 classes: thread c sums counts below it.
    if (tid < NC) {
        int s = 0;
        for (int c = 0; c < NC; ++c)
            s += (c < tid) ? cnt_t[c] : 0;
        start[tid] = s;
    }
    __syncthreads();

    // Scatter this thread's target into its class segment (unstable order OK:
    // selection below tracks the max original index g).
    {
        float4 t = imgs_box[b * GG + tid];
        int pos = start[tlab] + atomicAdd(&cursor[tlab], 1);
        float tw = fmaxf(t.z - t.x + 1.0f, 0.0f);
        float th = fmaxf(t.w - t.y + 1.0f, 0.0f);
        p0[pos] = t.x; p1[pos] = t.y; p2[pos] = t.z; p3[pos] = t.w;
        pa_s[pos] = tw * th;
        pg[pos] = tid;
    }
    __syncthreads();

    // ---- Main loop: one prediction per thread ----
    const int p = blockIdx.x * 256 + tid;
    const float4 pb = pre_box[b * PP + p];
    const int plab  = pre_label[b * PP + p];

    const float pw = fmaxf(pb.z - pb.x + 1.0f, 0.0f);
    const float ph = fmaxf(pb.w - pb.y + 1.0f, 0.0f);
    const float pa = pw * ph;
    const float inv_pa = 1.0f / pa;   // wh >= 1 -> pa > 0

    float sel = 0.0f;
    int   best_g = -1;

    const int st = start[plab];
    const int en = st + cnt_t[plab];
    for (int k = st; k < en; ++k) {
        const float t0 = p0[k], t1 = p1[k], t2 = p2[k], t3 = p3[k];
        const float iw = fmaxf(fminf(pb.z, t2) - fmaxf(pb.x, t0) + 1.0f, 0.0f);
        const float ih = fmaxf(fminf(pb.w, t3) - fmaxf(pb.y, t1) + 1.0f, 0.0f);
        const float inter = iw * ih;
        const float uni   = pa + pa_s[k] - inter;
        const float iou   = fmaxf(inter * inv_pa, 1e-6f);
        const float ow = fmaxf(fmaxf(pb.z, t2) - fminf(pb.x, t0) + 1.0f, 0.0f);
        const float oh = fmaxf(fmaxf(pb.w, t3) - fminf(pb.y, t1) + 1.0f, 0.0f);
        const float outer = ow * oh;
        float giou = iou - (outer - uni) / outer;
        giou = fminf(fmaxf(giou, -1.0f), 1.0f);
        const int g = pg[k];
        if (giou > 0.0f && g > best_g) { best_g = g; sel = giou; }
    }

    const float loss = (best_g >= 0) ? (1.0f - sel) : 0.0f;
    float v = (float)cnt_p[plab] * loss;

    // Block reduction: warp shuffle, then across the 8 warps.
    #pragma unroll
    for (int off = 16; off > 0; off >>= 1)
        v += __shfl_down_sync(0xFFFFFFFFu, v, off);
    const int warp = tid >> 5;
    const int lane = tid & 31;
    if (lane == 0) warp_sums[warp] = v;
    __syncthreads();
    if (warp == 0) {
        float s = (lane < 8) ? warp_sums[lane] : 0.0f;
        #pragma unroll
        for (int off = 4; off > 0; off >>= 1)
            s += __shfl_down_sync(0xFFFFFFFFu, s, off);
        if (lane == 0)
            g_partial[b * (PP / 256) + blockIdx.x] = s;
    }
}

// ---------------------------------------------------------------------------
// Kernel 2: deterministic final reduction of 256 partials -> scalar / BB.
// ---------------------------------------------------------------------------
__global__ void __launch_bounds__(256)
reduce_kernel(float* __restrict__ out) {
    __shared__ float warp_sums[8];
    const int tid = threadIdx.x;
    float v = g_partial[tid];
    #pragma unroll
    for (int off = 16; off > 0; off >>= 1)
        v += __shfl_down_sync(0xFFFFFFFFu, v, off);
    const int warp = tid >> 5;
    const int lane = tid & 31;
    if (lane == 0) warp_sums[warp] = v;
    __syncthreads();
    if (warp == 0) {
        float s = (lane < 8) ? warp_sums[lane] : 0.0f;
        #pragma unroll
        for (int off = 4; off > 0; off >>= 1)
            s += __shfl_down_sync(0xFFFFFFFFu, s, off);
        if (lane == 0)
            *out = s * (1.0f / (float)BB);
    }
}

// ---------------------------------------------------------------------------
// Harness entry. Input order per metadata: imgs_box, img_labels, pre_BOX,
// pre_label. Output: float32 scalar.
// ---------------------------------------------------------------------------
extern "C" void kernel_launch(void* const* d_in, const int* in_sizes, int n_in,
                              void* d_out, int out_size) {
    const float4* imgs_box   = (const float4*)d_in[0];
    const int*    img_labels = (const int*)   d_in[1];
    const float4* pre_box    = (const float4*)d_in[2];
    const int*    pre_label  = (const int*)   d_in[3];
    float* out = (float*)d_out;

    dim3 grid(PP / 256, BB);
    giou_kernel<<<grid, 256>>>(imgs_box, img_labels, pre_box, pre_label);
    reduce_kernel<<<1, 256>>>(out);
}

// round 5
// speedup vs baseline: 1.2657x; 1.2657x over previous
#include <cuda_runtime.h>
#include <cuda_bf16.h>

// Problem constants (fixed by setup_inputs)
#define BB 32
#define GG 256
#define PP 2048
#define NC 80

// Per-block partial sums + completion counter (single-kernel fused reduction)
#define NBLK ((PP / 256) * BB)   // 8 * 32 = 256
__device__ float g_partial[NBLK];
__device__ unsigned g_done = 0;  // reset to 0 by the last block each launch

// ---------------------------------------------------------------------------
// Fused kernel: class-compacted target lists, pre_label histogram (weights),
// GIoU against same-class targets only (tracking max original target index),
// per-block reduction, then last-block final reduction -> *out.
// Grid: (PP/256, BB) x 256 threads. One thread = one prediction.
// ---------------------------------------------------------------------------
__global__ void __launch_bounds__(256)
giou_kernel(const float4* __restrict__ imgs_box,
            const int*    __restrict__ img_labels,
            const float4* __restrict__ pre_box,
            const int*    __restrict__ pre_label,
            float*        __restrict__ out) {
    // Class-compacted target SoA (order within a class is arbitrary).
    __shared__ float p0[GG], p1[GG], p2[GG], p3[GG], pa_s[GG];
    __shared__ int   pg[GG];             // original target index g
    __shared__ int   cnt_t[NC];          // targets per class
    __shared__ int   start[96];          // exclusive prefix sum of cnt_t (padded)
    __shared__ int   cursor[NC];         // scatter cursors
    __shared__ int   cnt_p[NC];          // pre_label histogram (weights)
    __shared__ int   wtot[3];            // warp totals for the 96-lane scan
    __shared__ float warp_sums[8];
    __shared__ bool  is_last;

    const int b   = blockIdx.y;
    const int tid = threadIdx.x;
    const int warp = tid >> 5;
    const int lane = tid & 31;

    if (tid < NC) { cnt_t[tid] = 0; cursor[tid] = 0; cnt_p[tid] = 0; }
    __syncthreads();

    // Target label histogram (one target per thread).
    const int tlab = img_labels[b * GG + tid];
    atomicAdd(&cnt_t[tlab], 1);

    // Pre-label histogram for the weight lookup.
    {
        const int* lab = pre_label + b * PP;
        #pragma unroll
        for (int i = 0; i < PP / 256; ++i)
            atomicAdd(&cnt_p[lab[tid + i * 256]], 1);
    }
    __syncthreads();

    // Exclusive prefix sum over 80 classes via warp-shuffle scan (96 lanes).
    if (tid < 96) {
        int x = (tid < NC) ? cnt_t[tid] : 0;
        int incl = x;
        #pragma unroll
        for (int off = 1; off < 32; off <<= 1) {
            int y = __shfl_up_sync(0xFFFFFFFFu, incl, off);
            if (lane >= off) incl += y;
        }
        if (lane == 31) wtot[warp] = incl;
        __syncwarp();
        // cross-warp offsets resolved after syncthreads below
        start[tid] = incl - x;               // within-warp exclusive
    }
    __syncthreads();
    if (tid < 96 && warp > 0) {
        int add = wtot[0] + ((warp == 2) ? wtot[1] : 0);
        start[tid] += add;
    }
    __syncthreads();

    // Scatter this thread's target into its class segment (unstable order OK:
    // selection below tracks the max original index g).
    {
        float4 t = imgs_box[b * GG + tid];
        int pos = start[tlab] + atomicAdd(&cursor[tlab], 1);
        float tw = fmaxf(t.z - t.x + 1.0f, 0.0f);
        float th = fmaxf(t.w - t.y + 1.0f, 0.0f);
        p0[pos] = t.x; p1[pos] = t.y; p2[pos] = t.z; p3[pos] = t.w;
        pa_s[pos] = tw * th;
        pg[pos] = tid;
    }
    __syncthreads();

    // ---- Main loop: one prediction per thread ----
    const int p = blockIdx.x * 256 + tid;
    const float4 pb = pre_box[b * PP + p];
    const int plab  = pre_label[b * PP + p];

    const float pw = fmaxf(pb.z - pb.x + 1.0f, 0.0f);
    const float ph = fmaxf(pb.w - pb.y + 1.0f, 0.0f);
    const float pa = pw * ph;
    const float inv_pa = 1.0f / pa;   // wh >= 1 -> pa > 0

    float sel = 0.0f;
    int   best_g = -1;

    const int st = start[plab];
    const int en = st + cnt_t[plab];
    for (int k = st; k < en; ++k) {
        const float t0 = p0[k], t1 = p1[k], t2 = p2[k], t3 = p3[k];
        const float iw = fmaxf(fminf(pb.z, t2) - fmaxf(pb.x, t0) + 1.0f, 0.0f);
        const float ih = fmaxf(fminf(pb.w, t3) - fmaxf(pb.y, t1) + 1.0f, 0.0f);
        const float inter = iw * ih;
        const float uni   = pa + pa_s[k] - inter;
        const float iou   = fmaxf(inter * inv_pa, 1e-6f);
        const float ow = fmaxf(fmaxf(pb.z, t2) - fminf(pb.x, t0) + 1.0f, 0.0f);
        const float oh = fmaxf(fmaxf(pb.w, t3) - fminf(pb.y, t1) + 1.0f, 0.0f);
        const float outer = ow * oh;
        float giou = iou - (outer - uni) / outer;
        giou = fminf(fmaxf(giou, -1.0f), 1.0f);
        const int g = pg[k];
        if (giou > 0.0f && g > best_g) { best_g = g; sel = giou; }
    }

    const float loss = (best_g >= 0) ? (1.0f - sel) : 0.0f;
    float v = (float)cnt_p[plab] * loss;

    // Block reduction: warp shuffle, then across the 8 warps.
    #pragma unroll
    for (int off = 16; off > 0; off >>= 1)
        v += __shfl_down_sync(0xFFFFFFFFu, v, off);
    if (lane == 0) warp_sums[warp] = v;
    __syncthreads();
    if (warp == 0) {
        float s = (lane < 8) ? warp_sums[lane] : 0.0f;
        #pragma unroll
        for (int off = 4; off > 0; off >>= 1)
            s += __shfl_down_sync(0xFFFFFFFFu, s, off);
        if (lane == 0)
            g_partial[b * (PP / 256) + blockIdx.x] = s;
    }

    // ---- Last-block-done final reduction (saves a kernel launch) ----
    if (tid == 0) {
        __threadfence();                       // publish g_partial write
        unsigned t = atomicAdd(&g_done, 1u);
        is_last = (t == NBLK - 1);
    }
    __syncthreads();

    if (is_last) {
        // All other blocks fenced before arriving; L2 is coherent and this
        // block has never cached these lines in L1.
        float r = g_partial[tid];              // NBLK == 256 == blockDim
        #pragma unroll
        for (int off = 16; off > 0; off >>= 1)
            r += __shfl_down_sync(0xFFFFFFFFu, r, off);
        if (lane == 0) warp_sums[warp] = r;
        __syncthreads();
        if (warp == 0) {
            float s = (lane < 8) ? warp_sums[lane] : 0.0f;
            #pragma unroll
            for (int off = 4; off > 0; off >>= 1)
                s += __shfl_down_sync(0xFFFFFFFFu, s, off);
            if (lane == 0) {
                *out = s * (1.0f / (float)BB);
                g_done = 0;                    // reset for next graph replay
            }
        }
    }
}

// ---------------------------------------------------------------------------
// Harness entry. Input order per metadata: imgs_box, img_labels, pre_BOX,
// pre_label. Output: float32 scalar.
// ---------------------------------------------------------------------------
extern "C" void kernel_launch(void* const* d_in, const int* in_sizes, int n_in,
                              void* d_out, int out_size) {
    const float4* imgs_box   = (const float4*)d_in[0];
    const int*    img_labels = (const int*)   d_in[1];
    const float4* pre_box    = (const float4*)d_in[2];
    const int*    pre_label  = (const int*)   d_in[3];
    float* out = (float*)d_out;

    dim3 grid(PP / 256, BB);
    giou_kernel<<<grid, 256>>>(imgs_box, img_labels, pre_box, pre_label, out);
}